// round 15
// baseline (speedup 1.0000x reference)
#include <cuda_runtime.h>
#include <cuda_bf16.h>
#include <cuda_fp16.h>
#include <cstdint>
#include <math.h>

#define B      2
#define SEQ    2048
#define DIM    768
#define NHEADS 12
#define HDIM   64
#define MTOT   (B * SEQ)
#define SCALE  0.125f
#define LOG2E  1.4426950408889634f
#define KVPARTS 2
#define BLKS_PER_PART 16

// ---------------------------------------------------------------------------
// Scratch (allocation-free)
// ---------------------------------------------------------------------------
__device__ float g_V[MTOT * DIM];
__device__ float g_O1[MTOT * DIM];
__device__ float g_O2[MTOT * DIM];
__device__ float g_OM[MTOT * DIM];
__device__ float g_L[KVPARTS * MTOT * NHEADS];
__device__ uint32_t g_QH[MTOT * (DIM / 2)];   // fp16x2 Q (scaled, single-rounded)
__device__ uint32_t g_KH[MTOT * (DIM / 2)];   // fp16x2 K (single-rounded)
__device__ uint32_t g_VtH[B * NHEADS * HDIM * (SEQ / 2)];  // fp16x2 V^T
__device__ uint32_t g_WH[4 * DIM * (DIM / 2)];             // fp16x2 Wq|Wk|Wv|Wp

// ---------------------------------------------------------------------------
// helpers
// ---------------------------------------------------------------------------
__device__ __forceinline__ uint32_t h2_of(float a, float b) {
    __half2 h = __floats2half2_rn(a, b);
    return *reinterpret_cast<uint32_t*>(&h);
}
__device__ __forceinline__ void h2split2(float x, float y, uint32_t& hi, uint32_t& lo) {
    __half2 h = __floats2half2_rn(x, y);
    hi = *reinterpret_cast<uint32_t*>(&h);
    float2 hf = __half22float2(h);
    __half2 l = __floats2half2_rn(x - hf.x, y - hf.y);
    lo = *reinterpret_cast<uint32_t*>(&l);
}
__device__ __forceinline__ uint32_t exp2_ph(float s0, float s1) {
    uint32_t p;
    asm("{\n\t.reg .b32 t;\n\t"
        "cvt.rn.f16x2.f32 t, %2, %1;\n\t"
        "ex2.approx.f16x2 %0, t;\n\t}"
        : "=r"(p) : "f"(s0), "f"(s1));
    return p;
}
__device__ __forceinline__ uint32_t smem_u32(const void* p) {
    uint32_t a;
    asm("{ .reg .u64 t; cvta.to.shared.u64 t, %1; cvt.u32.u64 %0, t; }"
        : "=r"(a) : "l"(p));
    return a;
}
__device__ __forceinline__ void mma_f16(
    float* c, uint32_t a0, uint32_t a1, uint32_t a2, uint32_t a3,
    uint32_t b0, uint32_t b1)
{
    asm volatile(
        "mma.sync.aligned.m16n8k16.row.col.f32.f16.f16.f32 "
        "{%0,%1,%2,%3}, {%4,%5,%6,%7}, {%8,%9}, {%0,%1,%2,%3};"
        : "+f"(c[0]), "+f"(c[1]), "+f"(c[2]), "+f"(c[3])
        : "r"(a0), "r"(a1), "r"(a2), "r"(a3), "r"(b0), "r"(b1));
}

// ===========================================================================
// W pre-convert (unchanged)
// ===========================================================================
__global__ __launch_bounds__(256) void w_split(
    const float* __restrict__ W0, const float* __restrict__ W1,
    const float* __restrict__ W2, const float* __restrict__ W3,
    uint32_t* __restrict__ out)
{
    int z = blockIdx.y;
    const float* W = (z == 0) ? W0 : (z == 1) ? W1 : (z == 2) ? W2 : W3;
    size_t f = (size_t)blockIdx.x * 256 + threadIdx.x;
    float4 v = *(const float4*)(W + f * 4);
    *(uint2*)(out + (size_t)z * DIM * (DIM / 2) + f * 2) =
        make_uint2(h2_of(v.x, v.y), h2_of(v.z, v.w));
}

// ===========================================================================
// GEMM v4 (unchanged, known good)
// ===========================================================================
#define GAW 20

__global__ __launch_bounds__(256, 2) void gemm3_v4(
    const float* __restrict__ A0, const uint32_t* __restrict__ W0,
    float* __restrict__ C0, uint32_t* __restrict__ H0, uint32_t* __restrict__ L0,
    const float* __restrict__ A1, const uint32_t* __restrict__ W1,
    float* __restrict__ C1, uint32_t* __restrict__ H1, uint32_t* __restrict__ L1,
    const float* __restrict__ A2, const uint32_t* __restrict__ W2,
    float* __restrict__ C2, uint32_t* __restrict__ H2, uint32_t* __restrict__ L2,
    const float* __restrict__ bias, int mpack)
{
    __shared__ uint32_t Ah[64 * GAW];
    __shared__ uint32_t Al[64 * GAW];
    __shared__ uint32_t Wb[2][128 * GAW];

    const int tid  = threadIdx.x;
    const int wid  = tid >> 5;
    const int lane = tid & 31;
    const int g    = lane >> 2;
    const int t    = lane & 3;
    const int wm   = wid >> 2;
    const int wn   = wid & 3;
    const int m0   = blockIdx.y * 64;
    const int n0   = blockIdx.x * 128;
    const int z    = blockIdx.z;

    const float* A = A0; const uint32_t* W = W0; float* C = C0;
    uint32_t* XH = H0; uint32_t* XL = L0;
    if (z == 1) { A = A1; W = W1; C = C1; XH = H1; XL = L1; }
    else if (z == 2) { A = A2; W = W2; C = C2; XH = H2; XL = L2; }
    const int mode = (mpack >> (4 * z)) & 15;

    const uint32_t wb0 = smem_u32(&Wb[0][0]);

#define GCP16(dstb, srcp) \
    asm volatile("cp.async.cg.shared.global [%0], [%1], 16;" \
                 :: "r"(dstb), "l"(srcp))
#define ISSUE_W(ch) do { \
    uint32_t _base = wb0 + (((ch) & 1) ? 128u * GAW * 4u : 0u); \
    _Pragma("unroll") \
    for (int _i = 0; _i < 2; _i++) { \
        int _f = tid + 256 * _i; \
        int _r = _f >> 2, _w4 = (_f & 3) * 4; \
        GCP16(_base + (uint32_t)(_r * GAW + _w4) * 4u, \
              W + (size_t)(n0 + _r) * 384 + (ch) * 16 + _w4); \
    } \
} while (0)

    float acc[2][4][4];
#pragma unroll
    for (int i = 0; i < 2; i++)
#pragma unroll
        for (int j = 0; j < 4; j++)
#pragma unroll
            for (int e = 0; e < 4; e++) acc[i][j][e] = 0.0f;

    ISSUE_W(0);
    asm volatile("cp.async.commit_group;" ::: "memory");

    const int lr = tid >> 3;
    const int lc4 = (tid & 7) << 2;
    float4 pa[2];
#pragma unroll
    for (int i = 0; i < 2; i++)
        pa[i] = *(const float4*)(A + (size_t)(m0 + lr + 32 * i) * DIM + lc4);

    for (int ch = 0; ch < 24; ch++) {
        __syncthreads();
#pragma unroll
        for (int i = 0; i < 2; i++) {
            int r = lr + 32 * i;
            int wbase = r * GAW + (tid & 7) * 2;
            const float* av = &pa[i].x;
            uint32_t h0, l0, h1, l1;
            h2split2(av[0], av[1], h0, l0);
            h2split2(av[2], av[3], h1, l1);
            *(uint2*)(&Ah[wbase]) = make_uint2(h0, h1);
            *(uint2*)(&Al[wbase]) = make_uint2(l0, l1);
        }
        if (ch + 1 < 24) ISSUE_W(ch + 1);
        asm volatile("cp.async.commit_group;" ::: "memory");
        asm volatile("cp.async.wait_group 1;" ::: "memory");
        __syncthreads();

        if (ch + 1 < 24) {
            int k0 = (ch + 1) * 32;
#pragma unroll
            for (int i = 0; i < 2; i++)
                pa[i] = *(const float4*)(A + (size_t)(m0 + lr + 32 * i) * DIM + k0 + lc4);
        }

        const uint32_t* Wc = &Wb[ch & 1][0];
#pragma unroll
        for (int s = 0; s < 2; s++) {
            uint32_t bh[4][2];
#pragma unroll
            for (int j = 0; j < 4; j++) {
                int br = (wn * 32 + j * 8 + g) * GAW + s * 8 + t;
                bh[j][0] = Wc[br]; bh[j][1] = Wc[br + 4];
            }
#pragma unroll
            for (int i = 0; i < 2; i++) {
                int ar = (wm * 32 + i * 16 + g) * GAW + s * 8 + t;
                uint32_t ah0 = Ah[ar],     ah1 = Ah[ar + 8 * GAW];
                uint32_t ah2 = Ah[ar + 4], ah3 = Ah[ar + 8 * GAW + 4];
                uint32_t al0 = Al[ar],     al1 = Al[ar + 8 * GAW];
                uint32_t al2 = Al[ar + 4], al3 = Al[ar + 8 * GAW + 4];
#pragma unroll
                for (int j = 0; j < 4; j++) {
                    mma_f16(acc[i][j], ah0, ah1, ah2, ah3, bh[j][0], bh[j][1]);
                    mma_f16(acc[i][j], al0, al1, al2, al3, bh[j][0], bh[j][1]);
                }
            }
        }
    }

    if (mode == 0) {
#pragma unroll
        for (int j = 0; j < 4; j++) {
            int col = n0 + wn * 32 + j * 8 + 2 * t;
            float2 bv = make_float2(0.f, 0.f);
            if (bias) bv = *(const float2*)(bias + col);
#pragma unroll
            for (int i = 0; i < 2; i++) {
                int row = m0 + wm * 32 + i * 16 + g;
                *(float2*)(C + (size_t)row * DIM + col) =
                    make_float2(acc[i][j][0] + bv.x, acc[i][j][1] + bv.y);
                *(float2*)(C + (size_t)(row + 8) * DIM + col) =
                    make_float2(acc[i][j][2] + bv.x, acc[i][j][3] + bv.y);
            }
        }
    } else if (mode == 1) {
        const float sc = SCALE * LOG2E;
#pragma unroll
        for (int j = 0; j < 4; j++) {
            int wcol = (n0 + wn * 32 + j * 8 + 2 * t) >> 1;
#pragma unroll
            for (int i = 0; i < 2; i++) {
                int row = m0 + wm * 32 + i * 16 + g;
                XH[(size_t)row * 384 + wcol] =
                    h2_of(acc[i][j][0] * sc, acc[i][j][1] * sc);
                XH[(size_t)(row + 8) * 384 + wcol] =
                    h2_of(acc[i][j][2] * sc, acc[i][j][3] * sc);
            }
        }
    } else {
#pragma unroll
        for (int j = 0; j < 4; j++) {
            int wcol = (n0 + wn * 32 + j * 8 + 2 * t) >> 1;
#pragma unroll
            for (int i = 0; i < 2; i++) {
                int row = m0 + wm * 32 + i * 16 + g;
                XH[(size_t)row * 384 + wcol]       = h2_of(acc[i][j][0], acc[i][j][1]);
                XH[(size_t)(row + 8) * 384 + wcol] = h2_of(acc[i][j][2], acc[i][j][3]);
            }
        }
    }
#undef ISSUE_W
#undef GCP16
}

// ===========================================================================
// V -> V^T single fp16 (unchanged)
// ===========================================================================
__global__ __launch_bounds__(256) void v_split_t(
    const float* __restrict__ Vf, uint32_t* __restrict__ VtH)
{
    __shared__ float T[64 * 65];
    const int kv0 = blockIdx.x * 64;
    const int bh  = blockIdx.y;
    const int b   = bh / NHEADS, h = bh % NHEADS;
    const int tid = threadIdx.x;
    const float* src = Vf + ((size_t)b * SEQ + kv0) * DIM + h * HDIM;
#pragma unroll
    for (int i = 0; i < 4; i++) {
        int f = tid + 256 * i;
        int kv = f >> 4, c4 = (f & 15) * 4;
        float4 v = *(const float4*)(src + (size_t)kv * DIM + c4);
        T[kv * 65 + c4 + 0] = v.x;
        T[kv * 65 + c4 + 1] = v.y;
        T[kv * 65 + c4 + 2] = v.z;
        T[kv * 65 + c4 + 3] = v.w;
    }
    __syncthreads();
    uint32_t* dH = VtH + (size_t)bh * 64 * (SEQ / 2) + (kv0 >> 1);
#pragma unroll
    for (int i = 0; i < 8; i++) {
        int f = tid + 256 * i;
        int d = f >> 5, m = f & 31;
        dH[(size_t)d * (SEQ / 2) + m] =
            h2_of(T[(2 * m) * 65 + d], T[(2 * m + 1) * 65 + d]);
    }
}

// ===========================================================================
// Flash attention v9: software-pipelined. S(blk) + PV(blk-1) issue together;
// exp latency hidden behind PV. 4-stage cp.async ring (K|V per stage).
// FQ=128, single fp16 S and PV, l via ones-mma, split-KV x2.
// ===========================================================================
#define FQ 128
#define STG_W 4608         // K 2304 | VH 2304 (stride 36)
#define QH_W  18432        // after 4 stages
#define LS_W  23040
#define FSMW  23168        // 92672 bytes

__global__ __launch_bounds__(256, 1) void flash_mma9(
    const uint32_t* __restrict__ QH,
    const uint32_t* __restrict__ KH,
    const uint32_t* __restrict__ VtH,
    float* __restrict__ O1, float* __restrict__ O2,
    float* __restrict__ Lg)
{
    extern __shared__ uint32_t smw[];
    const uint32_t sb = smem_u32(smw);

    const int tid  = threadIdx.x;
    const int wid  = tid >> 5;
    const int lane = tid & 31;
    const int g    = lane >> 2;
    const int t    = lane & 3;
    const int wm   = wid >> 1;
    const int wn   = wid & 1;
    const int q0   = blockIdx.x * FQ;
    const int h    = blockIdx.y;
    const int part = blockIdx.z & 1;
    const int b    = blockIdx.z >> 1;

    float* Op = part ? O2 : O1;

    const uint32_t* QHr = QH + ((size_t)(b * SEQ + q0)) * 384 + 32 * h;
    const uint32_t* KHr = KH + ((size_t)b * SEQ) * 384 + 32 * h;
    const uint32_t* VHr = VtH + (size_t)(b * NHEADS + h) * 64 * (SEQ / 2);

    const int kvs = part * BLKS_PER_PART * 64;

#define CP16(dstw, srcp) \
    asm volatile("cp.async.cg.shared.global [%0], [%1], 16;" \
                 :: "r"(sb + (uint32_t)(dstw) * 4u), "l"(srcp))
#define ISSUE_BLK(blk) do { \
    int _kv0 = kvs + (blk) * 64; \
    int _bw  = ((blk) & 3) * STG_W; \
    _Pragma("unroll") \
    for (int _i = 0; _i < 2; _i++) { \
        int _f = tid + 256 * _i; \
        int _r = _f >> 3, _w4 = (_f & 7) * 4; \
        CP16(_bw + _r * 36 + _w4,        KHr + ((size_t)(_kv0 + _r)) * 384 + _w4); \
        CP16(_bw + 2304 + _r * 36 + _w4, VHr + (size_t)_r * (SEQ / 2) + (_kv0 >> 1) + _w4); \
    } \
} while (0)

// S(blk): 32 mmas into s[][][] from K stage
#define DO_S(Ksh) do { \
    _Pragma("unroll") \
    for (int mi = 0; mi < 2; mi++) \
        _Pragma("unroll") \
        for (int j = 0; j < 4; j++) \
            _Pragma("unroll") \
            for (int e = 0; e < 4; e++) s[mi][j][e] = 0.0f; \
    _Pragma("unroll") \
    for (int kt = 0; kt < 4; kt++) { \
        _Pragma("unroll") \
        for (int jn = 0; jn < 4; jn++) { \
            int wbase = (32 * wn + 8 * jn + g) * 36 + 8 * kt + t; \
            uint32_t b0 = (Ksh)[wbase], b1 = (Ksh)[wbase + 4]; \
            _Pragma("unroll") \
            for (int mi = 0; mi < 2; mi++) \
                mma_f16(s[mi][jn], qh[mi][kt][0], qh[mi][kt][1], \
                        qh[mi][kt][2], qh[mi][kt][3], b0, b1); \
        } \
    } \
} while (0)

// PV with php from previous block against V stage
#define DO_PV(Vth) do { \
    _Pragma("unroll") \
    for (int jk = 0; jk < 2; jk++) { \
        _Pragma("unroll") \
        for (int jnd = 0; jnd < 8; jnd++) { \
            int vr = 8 * jnd + g; \
            int cb = 16 * wn + 8 * jk + t; \
            uint32_t vh0 = (Vth)[vr * 36 + cb], vh1 = (Vth)[vr * 36 + cb + 4]; \
            _Pragma("unroll") \
            for (int mi = 0; mi < 2; mi++) \
                mma_f16(acc_o[mi][jnd], \
                        php[mi][2 * jk][0], php[mi][2 * jk][1], \
                        php[mi][2 * jk + 1][0], php[mi][2 * jk + 1][1], vh0, vh1); \
        } \
    } \
} while (0)

// exp + l-mma, fills php from s
#define DO_EXP_L() do { \
    _Pragma("unroll") \
    for (int mi = 0; mi < 2; mi++) \
        _Pragma("unroll") \
        for (int jn = 0; jn < 4; jn++) { \
            php[mi][jn][0] = exp2_ph(s[mi][jn][0], s[mi][jn][1]); \
            php[mi][jn][1] = exp2_ph(s[mi][jn][2], s[mi][jn][3]); \
        } \
    _Pragma("unroll") \
    for (int mi = 0; mi < 2; mi++) \
        _Pragma("unroll") \
        for (int jk = 0; jk < 2; jk++) \
            mma_f16(acc_l[mi], \
                    php[mi][2 * jk][0], php[mi][2 * jk][1], \
                    php[mi][2 * jk + 1][0], php[mi][2 * jk + 1][1], \
                    ONES, ONES); \
} while (0)

    ISSUE_BLK(0);
    asm volatile("cp.async.commit_group;" ::: "memory");
    ISSUE_BLK(1);
    asm volatile("cp.async.commit_group;" ::: "memory");

    // stage Q (128 rows x 32 words)
#pragma unroll
    for (int i = 0; i < 4; i++) {
        int f = tid + 256 * i;
        int q = f >> 3, w4 = (f & 7) * 4;
        uint4 a = *(const uint4*)(QHr + (size_t)q * 384 + w4);
        *(uint4*)(&smw[QH_W + q * 36 + w4]) = a;
    }
    __syncthreads();

    uint32_t qh[2][4][4];
#pragma unroll
    for (int mi = 0; mi < 2; mi++)
#pragma unroll
        for (int kt = 0; kt < 4; kt++) {
            int base = QH_W + (32 * wm + 16 * mi + g) * 36 + 8 * kt + t;
            qh[mi][kt][0] = smw[base];
            qh[mi][kt][1] = smw[base + 8 * 36];
            qh[mi][kt][2] = smw[base + 4];
            qh[mi][kt][3] = smw[base + 8 * 36 + 4];
        }

    float acc_o[2][8][4];
#pragma unroll
    for (int mi = 0; mi < 2; mi++)
#pragma unroll
        for (int j = 0; j < 8; j++)
#pragma unroll
            for (int e = 0; e < 4; e++) acc_o[mi][j][e] = 0.0f;
    float acc_l[2][4];
#pragma unroll
    for (int mi = 0; mi < 2; mi++)
#pragma unroll
        for (int e = 0; e < 4; e++) acc_l[mi][e] = 0.0f;

    const uint32_t ONES = 0x3C003C00u;
    float s[2][4][4];
    uint32_t php[2][4][2];

    // ---- pre-loop: block 0 (S + exp only) ----
    asm volatile("cp.async.wait_group 1;" ::: "memory");
    __syncthreads();
    DO_S(smw);                       // stage 0
    DO_EXP_L();
    ISSUE_BLK(2);
    asm volatile("cp.async.commit_group;" ::: "memory");

    // ---- pipelined mainloop ----
    for (int blk = 1; blk < BLKS_PER_PART; blk++) {
        asm volatile("cp.async.wait_group 1;" ::: "memory");
        __syncthreads();   // stage blk ready; all warps done reading stage blk-2

        const uint32_t* Ksh   = smw + (blk & 3) * STG_W;
        const uint32_t* Vprev = smw + ((blk - 1) & 3) * STG_W + 2304;

        DO_S(Ksh);          // independent tensor work...
        DO_PV(Vprev);       // ...covers the S->exp latency
        DO_EXP_L();

        if (blk + 2 < BLKS_PER_PART) ISSUE_BLK(blk + 2);
        asm volatile("cp.async.commit_group;" ::: "memory");
    }

    // ---- drain: PV of the last block ----
    {
        const uint32_t* Vlast = smw + ((BLKS_PER_PART - 1) & 3) * STG_W + 2304;
        DO_PV(Vlast);
    }

    float l_loc[4];
#pragma unroll
    for (int mi = 0; mi < 2; mi++) {
        l_loc[2 * mi]     = acc_l[mi][0];
        l_loc[2 * mi + 1] = acc_l[mi][2];
    }

    // ---- cross-warp merge ----
    __syncthreads();
    float* OmS = (float*)smw;
    float* lS  = (float*)(smw + LS_W);
    const size_t head_off = (size_t)b * SEQ * DIM + (size_t)h * HDIM;
    if (wn == 1) {
#pragma unroll
        for (int mi = 0; mi < 2; mi++)
#pragma unroll
            for (int jnd = 0; jnd < 8; jnd++) {
                int r = 32 * wm + 16 * mi + g;
                int c = 8 * jnd + 2 * t;
                *(float2*)(&OmS[r * 68 + c]) =
                    make_float2(acc_o[mi][jnd][0], acc_o[mi][jnd][1]);
                *(float2*)(&OmS[(r + 8) * 68 + c]) =
                    make_float2(acc_o[mi][jnd][2], acc_o[mi][jnd][3]);
            }
        if (t == 0) {
            lS[32 * wm + g]      = l_loc[0];
            lS[32 * wm + 8 + g]  = l_loc[1];
            lS[32 * wm + 16 + g] = l_loc[2];
            lS[32 * wm + 24 + g] = l_loc[3];
        }
    }
    __syncthreads();
    if (wn == 0) {
        float* Obase = Op + head_off + (size_t)q0 * DIM;
#pragma unroll
        for (int mi = 0; mi < 2; mi++)
#pragma unroll
            for (int jnd = 0; jnd < 8; jnd++) {
                int r = 32 * wm + 16 * mi + g;
                int c = 8 * jnd + 2 * t;
                float2 p0 = *(const float2*)(&OmS[r * 68 + c]);
                float2 p1 = *(const float2*)(&OmS[(r + 8) * 68 + c]);
                *(float2*)(Obase + (size_t)r * DIM + c) =
                    make_float2(acc_o[mi][jnd][0] + p0.x, acc_o[mi][jnd][1] + p0.y);
                *(float2*)(Obase + (size_t)(r + 8) * DIM + c) =
                    make_float2(acc_o[mi][jnd][2] + p1.x, acc_o[mi][jnd][3] + p1.y);
            }
        if (t == 0) {
            int rows[4] = {32 * wm + g, 32 * wm + 8 + g, 32 * wm + 16 + g, 32 * wm + 24 + g};
#pragma unroll
            for (int sl = 0; sl < 4; sl++) {
                float ltot = l_loc[sl] + lS[rows[sl]];
                int grow = b * SEQ + q0 + rows[sl];
                Lg[(size_t)part * MTOT * NHEADS + (size_t)grow * NHEADS + h] = ltot;
            }
        }
    }
#undef DO_EXP_L
#undef DO_PV
#undef DO_S
#undef ISSUE_BLK
#undef CP16
}

// ===========================================================================
// Merge + normalize the 2 kv-partitions (unchanged)
// ===========================================================================
__global__ __launch_bounds__(256) void merge_norm2(
    const float* __restrict__ O1, const float* __restrict__ O2,
    const float* __restrict__ Lg, float* __restrict__ Om)
{
    int f = blockIdx.x * 256 + threadIdx.x;
    int row = f / (DIM / 4);
    int c4  = (f % (DIM / 4)) * 4;
    int h   = c4 >> 6;
    size_t li = (size_t)row * NHEADS + h;
    float l = Lg[li] + Lg[(size_t)MTOT * NHEADS + li];
    float inv = 1.0f / l;
    float4 a = *(const float4*)(O1 + (size_t)f * 4);
    float4 bq = *(const float4*)(O2 + (size_t)f * 4);
    float4 o;
    o.x = (a.x + bq.x) * inv;
    o.y = (a.y + bq.y) * inv;
    o.z = (a.z + bq.z) * inv;
    o.w = (a.w + bq.w) * inv;
    *(float4*)(Om + (size_t)f * 4) = o;
}

// ---------------------------------------------------------------------------
// Launch
// ---------------------------------------------------------------------------
extern "C" void kernel_launch(void* const* d_in, const int* in_sizes, int n_in,
                              void* d_out, int out_size)
{
    const float* xq = (const float*)d_in[0];
    const float* xk = (const float*)d_in[1];
    const float* xv = (const float*)d_in[2];
    const float* Wq = (const float*)d_in[3];
    const float* Wk = (const float*)d_in[4];
    const float* Wv = (const float*)d_in[5];
    const float* Wp = (const float*)d_in[6];
    const float* bp = (const float*)d_in[7];
    float* out = (float*)d_out;

    float *vb, *o1, *o2, *om, *lg;
    uint32_t *qhp, *khp, *vhp, *whp;
    cudaGetSymbolAddress((void**)&vb, g_V);
    cudaGetSymbolAddress((void**)&o1, g_O1);
    cudaGetSymbolAddress((void**)&o2, g_O2);
    cudaGetSymbolAddress((void**)&om, g_OM);
    cudaGetSymbolAddress((void**)&lg, g_L);
    cudaGetSymbolAddress((void**)&qhp, g_QH);
    cudaGetSymbolAddress((void**)&khp, g_KH);
    cudaGetSymbolAddress((void**)&vhp, g_VtH);
    cudaGetSymbolAddress((void**)&whp, g_WH);

    const size_t WSTR = (size_t)DIM * (DIM / 2);

    w_split<<<dim3(DIM * DIM / 4 / 256, 4), 256>>>(Wq, Wk, Wv, Wp, whp);

    gemm3_v4<<<dim3(6, 64, 3), 256>>>(
        xq, whp,            nullptr, qhp, nullptr,
        xk, whp + WSTR,     nullptr, khp, nullptr,
        xv, whp + 2 * WSTR, vb, nullptr, nullptr,
        nullptr, 0x021);

    v_split_t<<<dim3(SEQ / 64, B * NHEADS), 256>>>(vb, vhp);

    const int fsm_bytes = FSMW * 4;   // 92672
    cudaFuncSetAttribute(flash_mma9,
                         cudaFuncAttributeMaxDynamicSharedMemorySize, fsm_bytes);
    flash_mma9<<<dim3(SEQ / FQ, NHEADS, B * KVPARTS), 256, fsm_bytes>>>(
        qhp, khp, vhp, o1, o2, lg);

    merge_norm2<<<(MTOT * DIM / 4) / 256, 256>>>(o1, o2, lg, om);

    gemm3_v4<<<dim3(6, 64, 1), 256>>>(
        om, whp + 3 * WSTR, out, nullptr, nullptr,
        om, whp + 3 * WSTR, out, nullptr, nullptr,
        om, whp + 3 * WSTR, out, nullptr, nullptr,
        bp, 0x000);
}

// round 16
// speedup vs baseline: 1.0267x; 1.0267x over previous
#include <cuda_runtime.h>
#include <cuda_bf16.h>
#include <cuda_fp16.h>
#include <cstdint>
#include <math.h>

#define B      2
#define SEQ    2048
#define DIM    768
#define NHEADS 12
#define HDIM   64
#define MTOT   (B * SEQ)
#define SCALE  0.125f
#define LOG2E  1.4426950408889634f
#define KVPARTS 3
#define BLKS_PER_PART 11

// ---------------------------------------------------------------------------
// Scratch (allocation-free)
// ---------------------------------------------------------------------------
__device__ float g_V[MTOT * DIM];
__device__ float g_O1[MTOT * DIM];
__device__ float g_O2[MTOT * DIM];
__device__ float g_O3[MTOT * DIM];
__device__ float g_OM[MTOT * DIM];
__device__ float g_L[KVPARTS * MTOT * NHEADS];
__device__ uint32_t g_QH[MTOT * (DIM / 2)];   // fp16x2 Q (scaled, single-rounded)
__device__ uint32_t g_KH[MTOT * (DIM / 2)];   // fp16x2 K (single-rounded)
__device__ uint32_t g_VtH[B * NHEADS * HDIM * (SEQ / 2)];  // fp16x2 V^T
__device__ uint32_t g_WH[4 * DIM * (DIM / 2)];             // fp16x2 Wq|Wk|Wv|Wp

// ---------------------------------------------------------------------------
// helpers
// ---------------------------------------------------------------------------
__device__ __forceinline__ uint32_t h2_of(float a, float b) {
    __half2 h = __floats2half2_rn(a, b);
    return *reinterpret_cast<uint32_t*>(&h);
}
__device__ __forceinline__ void h2split2(float x, float y, uint32_t& hi, uint32_t& lo) {
    __half2 h = __floats2half2_rn(x, y);
    hi = *reinterpret_cast<uint32_t*>(&h);
    float2 hf = __half22float2(h);
    __half2 l = __floats2half2_rn(x - hf.x, y - hf.y);
    lo = *reinterpret_cast<uint32_t*>(&l);
}
__device__ __forceinline__ uint32_t exp2_ph(float s0, float s1) {
    uint32_t p;
    asm("{\n\t.reg .b32 t;\n\t"
        "cvt.rn.f16x2.f32 t, %2, %1;\n\t"
        "ex2.approx.f16x2 %0, t;\n\t}"
        : "=r"(p) : "f"(s0), "f"(s1));
    return p;
}
__device__ __forceinline__ uint32_t smem_u32(const void* p) {
    uint32_t a;
    asm("{ .reg .u64 t; cvta.to.shared.u64 t, %1; cvt.u32.u64 %0, t; }"
        : "=r"(a) : "l"(p));
    return a;
}
__device__ __forceinline__ void mma_f16(
    float* c, uint32_t a0, uint32_t a1, uint32_t a2, uint32_t a3,
    uint32_t b0, uint32_t b1)
{
    asm volatile(
        "mma.sync.aligned.m16n8k16.row.col.f32.f16.f16.f32 "
        "{%0,%1,%2,%3}, {%4,%5,%6,%7}, {%8,%9}, {%0,%1,%2,%3};"
        : "+f"(c[0]), "+f"(c[1]), "+f"(c[2]), "+f"(c[3])
        : "r"(a0), "r"(a1), "r"(a2), "r"(a3), "r"(b0), "r"(b1));
}
__device__ __forceinline__ void ldsm_x4(uint32_t* r, uint32_t addr) {
    asm volatile(
        "ldmatrix.sync.aligned.m8n8.x4.shared.b16 {%0,%1,%2,%3}, [%4];"
        : "=r"(r[0]), "=r"(r[1]), "=r"(r[2]), "=r"(r[3]) : "r"(addr));
}

// ===========================================================================
// W pre-convert (unchanged)
// ===========================================================================
__global__ __launch_bounds__(256) void w_split(
    const float* __restrict__ W0, const float* __restrict__ W1,
    const float* __restrict__ W2, const float* __restrict__ W3,
    uint32_t* __restrict__ out)
{
    int z = blockIdx.y;
    const float* W = (z == 0) ? W0 : (z == 1) ? W1 : (z == 2) ? W2 : W3;
    size_t f = (size_t)blockIdx.x * 256 + threadIdx.x;
    float4 v = *(const float4*)(W + f * 4);
    *(uint2*)(out + (size_t)z * DIM * (DIM / 2) + f * 2) =
        make_uint2(h2_of(v.x, v.y), h2_of(v.z, v.w));
}

// ===========================================================================
// GEMM v4 (unchanged, known good)
// ===========================================================================
#define GAW 20

__global__ __launch_bounds__(256, 2) void gemm3_v4(
    const float* __restrict__ A0, const uint32_t* __restrict__ W0,
    float* __restrict__ C0, uint32_t* __restrict__ H0, uint32_t* __restrict__ L0,
    const float* __restrict__ A1, const uint32_t* __restrict__ W1,
    float* __restrict__ C1, uint32_t* __restrict__ H1, uint32_t* __restrict__ L1,
    const float* __restrict__ A2, const uint32_t* __restrict__ W2,
    float* __restrict__ C2, uint32_t* __restrict__ H2, uint32_t* __restrict__ L2,
    const float* __restrict__ bias, int mpack)
{
    __shared__ uint32_t Ah[64 * GAW];
    __shared__ uint32_t Al[64 * GAW];
    __shared__ uint32_t Wb[2][128 * GAW];

    const int tid  = threadIdx.x;
    const int wid  = tid >> 5;
    const int lane = tid & 31;
    const int g    = lane >> 2;
    const int t    = lane & 3;
    const int wm   = wid >> 2;
    const int wn   = wid & 3;
    const int m0   = blockIdx.y * 64;
    const int n0   = blockIdx.x * 128;
    const int z    = blockIdx.z;

    const float* A = A0; const uint32_t* W = W0; float* C = C0;
    uint32_t* XH = H0; uint32_t* XL = L0;
    if (z == 1) { A = A1; W = W1; C = C1; XH = H1; XL = L1; }
    else if (z == 2) { A = A2; W = W2; C = C2; XH = H2; XL = L2; }
    const int mode = (mpack >> (4 * z)) & 15;

    const uint32_t wb0 = smem_u32(&Wb[0][0]);

#define GCP16(dstb, srcp) \
    asm volatile("cp.async.cg.shared.global [%0], [%1], 16;" \
                 :: "r"(dstb), "l"(srcp))
#define ISSUE_W(ch) do { \
    uint32_t _base = wb0 + (((ch) & 1) ? 128u * GAW * 4u : 0u); \
    _Pragma("unroll") \
    for (int _i = 0; _i < 2; _i++) { \
        int _f = tid + 256 * _i; \
        int _r = _f >> 2, _w4 = (_f & 3) * 4; \
        GCP16(_base + (uint32_t)(_r * GAW + _w4) * 4u, \
              W + (size_t)(n0 + _r) * 384 + (ch) * 16 + _w4); \
    } \
} while (0)

    float acc[2][4][4];
#pragma unroll
    for (int i = 0; i < 2; i++)
#pragma unroll
        for (int j = 0; j < 4; j++)
#pragma unroll
            for (int e = 0; e < 4; e++) acc[i][j][e] = 0.0f;

    ISSUE_W(0);
    asm volatile("cp.async.commit_group;" ::: "memory");

    const int lr = tid >> 3;
    const int lc4 = (tid & 7) << 2;
    float4 pa[2];
#pragma unroll
    for (int i = 0; i < 2; i++)
        pa[i] = *(const float4*)(A + (size_t)(m0 + lr + 32 * i) * DIM + lc4);

    for (int ch = 0; ch < 24; ch++) {
        __syncthreads();
#pragma unroll
        for (int i = 0; i < 2; i++) {
            int r = lr + 32 * i;
            int wbase = r * GAW + (tid & 7) * 2;
            const float* av = &pa[i].x;
            uint32_t h0, l0, h1, l1;
            h2split2(av[0], av[1], h0, l0);
            h2split2(av[2], av[3], h1, l1);
            *(uint2*)(&Ah[wbase]) = make_uint2(h0, h1);
            *(uint2*)(&Al[wbase]) = make_uint2(l0, l1);
        }
        if (ch + 1 < 24) ISSUE_W(ch + 1);
        asm volatile("cp.async.commit_group;" ::: "memory");
        asm volatile("cp.async.wait_group 1;" ::: "memory");
        __syncthreads();

        if (ch + 1 < 24) {
            int k0 = (ch + 1) * 32;
#pragma unroll
            for (int i = 0; i < 2; i++)
                pa[i] = *(const float4*)(A + (size_t)(m0 + lr + 32 * i) * DIM + k0 + lc4);
        }

        const uint32_t* Wc = &Wb[ch & 1][0];
#pragma unroll
        for (int s = 0; s < 2; s++) {
            uint32_t bh[4][2];
#pragma unroll
            for (int j = 0; j < 4; j++) {
                int br = (wn * 32 + j * 8 + g) * GAW + s * 8 + t;
                bh[j][0] = Wc[br]; bh[j][1] = Wc[br + 4];
            }
#pragma unroll
            for (int i = 0; i < 2; i++) {
                int ar = (wm * 32 + i * 16 + g) * GAW + s * 8 + t;
                uint32_t ah0 = Ah[ar],     ah1 = Ah[ar + 8 * GAW];
                uint32_t ah2 = Ah[ar + 4], ah3 = Ah[ar + 8 * GAW + 4];
                uint32_t al0 = Al[ar],     al1 = Al[ar + 8 * GAW];
                uint32_t al2 = Al[ar + 4], al3 = Al[ar + 8 * GAW + 4];
#pragma unroll
                for (int j = 0; j < 4; j++) {
                    mma_f16(acc[i][j], ah0, ah1, ah2, ah3, bh[j][0], bh[j][1]);
                    mma_f16(acc[i][j], al0, al1, al2, al3, bh[j][0], bh[j][1]);
                }
            }
        }
    }

    if (mode == 0) {
#pragma unroll
        for (int j = 0; j < 4; j++) {
            int col = n0 + wn * 32 + j * 8 + 2 * t;
            float2 bv = make_float2(0.f, 0.f);
            if (bias) bv = *(const float2*)(bias + col);
#pragma unroll
            for (int i = 0; i < 2; i++) {
                int row = m0 + wm * 32 + i * 16 + g;
                *(float2*)(C + (size_t)row * DIM + col) =
                    make_float2(acc[i][j][0] + bv.x, acc[i][j][1] + bv.y);
                *(float2*)(C + (size_t)(row + 8) * DIM + col) =
                    make_float2(acc[i][j][2] + bv.x, acc[i][j][3] + bv.y);
            }
        }
    } else if (mode == 1) {
        const float sc = SCALE * LOG2E;
#pragma unroll
        for (int j = 0; j < 4; j++) {
            int wcol = (n0 + wn * 32 + j * 8 + 2 * t) >> 1;
#pragma unroll
            for (int i = 0; i < 2; i++) {
                int row = m0 + wm * 32 + i * 16 + g;
                XH[(size_t)row * 384 + wcol] =
                    h2_of(acc[i][j][0] * sc, acc[i][j][1] * sc);
                XH[(size_t)(row + 8) * 384 + wcol] =
                    h2_of(acc[i][j][2] * sc, acc[i][j][3] * sc);
            }
        }
    } else {
#pragma unroll
        for (int j = 0; j < 4; j++) {
            int wcol = (n0 + wn * 32 + j * 8 + 2 * t) >> 1;
#pragma unroll
            for (int i = 0; i < 2; i++) {
                int row = m0 + wm * 32 + i * 16 + g;
                XH[(size_t)row * 384 + wcol]       = h2_of(acc[i][j][0], acc[i][j][1]);
                XH[(size_t)(row + 8) * 384 + wcol] = h2_of(acc[i][j][2], acc[i][j][3]);
            }
        }
    }
#undef ISSUE_W
#undef GCP16
}

// ===========================================================================
// V -> V^T single fp16 (unchanged)
// ===========================================================================
__global__ __launch_bounds__(256) void v_split_t(
    const float* __restrict__ Vf, uint32_t* __restrict__ VtH)
{
    __shared__ float T[64 * 65];
    const int kv0 = blockIdx.x * 64;
    const int bh  = blockIdx.y;
    const int b   = bh / NHEADS, h = bh % NHEADS;
    const int tid = threadIdx.x;
    const float* src = Vf + ((size_t)b * SEQ + kv0) * DIM + h * HDIM;
#pragma unroll
    for (int i = 0; i < 4; i++) {
        int f = tid + 256 * i;
        int kv = f >> 4, c4 = (f & 15) * 4;
        float4 v = *(const float4*)(src + (size_t)kv * DIM + c4);
        T[kv * 65 + c4 + 0] = v.x;
        T[kv * 65 + c4 + 1] = v.y;
        T[kv * 65 + c4 + 2] = v.z;
        T[kv * 65 + c4 + 3] = v.w;
    }
    __syncthreads();
    uint32_t* dH = VtH + (size_t)bh * 64 * (SEQ / 2) + (kv0 >> 1);
#pragma unroll
    for (int i = 0; i < 8; i++) {
        int f = tid + 256 * i;
        int d = f >> 5, m = f & 31;
        dH[(size_t)d * (SEQ / 2) + m] =
            h2_of(T[(2 * m) * 65 + d], T[(2 * m + 1) * 65 + d]);
    }
}

// ===========================================================================
// Flash attention v10: R14 structure + ldmatrix.x4 fragment loads,
// split-KV x3 (11/11/10 blocks). Single fp16 S and PV, ones-mma l.
// ===========================================================================
#define FQ 128
#define STG_W 4608         // K 2304 | VH 2304 (stride 36)
#define QH_W  13824        // Q stage after 3 stages
#define LS_W  18432
#define FSMW  18560        // 74240 bytes

__global__ __launch_bounds__(256, 1) void flash_mma10(
    const uint32_t* __restrict__ QH,
    const uint32_t* __restrict__ KH,
    const uint32_t* __restrict__ VtH,
    float* __restrict__ O1, float* __restrict__ O2, float* __restrict__ O3,
    float* __restrict__ Lg)
{
    extern __shared__ uint32_t smw[];
    const uint32_t sb = smem_u32(smw);

    const int tid  = threadIdx.x;
    const int wid  = tid >> 5;
    const int lane = tid & 31;
    const int g    = lane >> 2;
    const int t    = lane & 3;
    const int r8   = lane & 7;      // ldmatrix row within tile
    const int grp  = lane >> 3;     // ldmatrix tile selector
    const int wm   = wid >> 1;
    const int wn   = wid & 1;
    const int q0   = blockIdx.x * FQ;
    const int h    = blockIdx.y;
    const int part = blockIdx.z % KVPARTS;
    const int b    = blockIdx.z / KVPARTS;

    float* Op = (part == 0) ? O1 : ((part == 1) ? O2 : O3);

    const uint32_t* QHr = QH + ((size_t)(b * SEQ + q0)) * 384 + 32 * h;
    const uint32_t* KHr = KH + ((size_t)b * SEQ) * 384 + 32 * h;
    const uint32_t* VHr = VtH + (size_t)(b * NHEADS + h) * 64 * (SEQ / 2);

    const int kvs  = part * BLKS_PER_PART * 64;
    const int kve  = min(SEQ, kvs + BLKS_PER_PART * 64);
    const int nblk = (kve - kvs) >> 6;

    // per-lane ldmatrix word offsets (within a stage)
    const uint32_t ks_off = (uint32_t)((32 * wn + r8) * 36 + 8 * (grp >> 1) + 4 * (grp & 1));
    const uint32_t vs_off = (uint32_t)(r8 * 36 + 16 * wn + 8 * (grp >> 1) + 4 * (grp & 1));

#define CP16(dstw, srcp) \
    asm volatile("cp.async.cg.shared.global [%0], [%1], 16;" \
                 :: "r"(sb + (uint32_t)(dstw) * 4u), "l"(srcp))
#define ISSUE_BLK(blk) do { \
    int _kv0 = kvs + (blk) * 64; \
    int _bw  = ((blk) % 3) * STG_W; \
    _Pragma("unroll") \
    for (int _i = 0; _i < 2; _i++) { \
        int _f = tid + 256 * _i; \
        int _r = _f >> 3, _w4 = (_f & 7) * 4; \
        CP16(_bw + _r * 36 + _w4,        KHr + ((size_t)(_kv0 + _r)) * 384 + _w4); \
        CP16(_bw + 2304 + _r * 36 + _w4, VHr + (size_t)_r * (SEQ / 2) + (_kv0 >> 1) + _w4); \
    } \
} while (0)

    ISSUE_BLK(0);
    asm volatile("cp.async.commit_group;" ::: "memory");
    ISSUE_BLK(1);
    asm volatile("cp.async.commit_group;" ::: "memory");

    // stage Q (128 rows x 32 words)
#pragma unroll
    for (int i = 0; i < 4; i++) {
        int f = tid + 256 * i;
        int q = f >> 3, w4 = (f & 7) * 4;
        uint4 a = *(const uint4*)(QHr + (size_t)q * 384 + w4);
        *(uint4*)(&smw[QH_W + q * 36 + w4]) = a;
    }
    __syncthreads();

    uint32_t qh[2][4][4];
#pragma unroll
    for (int mi = 0; mi < 2; mi++)
#pragma unroll
        for (int kt = 0; kt < 4; kt++) {
            int base = QH_W + (32 * wm + 16 * mi + g) * 36 + 8 * kt + t;
            qh[mi][kt][0] = smw[base];
            qh[mi][kt][1] = smw[base + 8 * 36];
            qh[mi][kt][2] = smw[base + 4];
            qh[mi][kt][3] = smw[base + 8 * 36 + 4];
        }

    float acc_o[2][8][4];
#pragma unroll
    for (int mi = 0; mi < 2; mi++)
#pragma unroll
        for (int j = 0; j < 8; j++)
#pragma unroll
            for (int e = 0; e < 4; e++) acc_o[mi][j][e] = 0.0f;
    float acc_l[2][4];
#pragma unroll
    for (int mi = 0; mi < 2; mi++)
#pragma unroll
        for (int e = 0; e < 4; e++) acc_l[mi][e] = 0.0f;

    const uint32_t ONES = 0x3C003C00u;

    for (int blk = 0; blk < nblk; blk++) {
        asm volatile("cp.async.wait_group 1;" ::: "memory");
        __syncthreads();

        const uint32_t kBase = sb + (uint32_t)((blk % 3) * STG_W) * 4u;
        const uint32_t vBase = kBase + 2304u * 4u;

        // ---- S = Q @ K^T (ldmatrix.x4: per jn, 2 loads cover 4 kt) ----
        float s[2][4][4];
#pragma unroll
        for (int mi = 0; mi < 2; mi++)
#pragma unroll
            for (int j = 0; j < 4; j++)
#pragma unroll
                for (int e = 0; e < 4; e++) s[mi][j][e] = 0.0f;

#pragma unroll
        for (int jn = 0; jn < 4; jn++) {
            uint32_t bb[8];
            uint32_t a0 = kBase + (ks_off + (uint32_t)(jn * 8 * 36)) * 4u;
            ldsm_x4(&bb[0], a0);            // kt 0,1
            ldsm_x4(&bb[4], a0 + 64u);      // kt 2,3 (+16 words)
#pragma unroll
            for (int kt = 0; kt < 4; kt++)
#pragma unroll
                for (int mi = 0; mi < 2; mi++)
                    mma_f16(s[mi][jn], qh[mi][kt][0], qh[mi][kt][1],
                            qh[mi][kt][2], qh[mi][kt][3],
                            bb[kt * 2], bb[kt * 2 + 1]);
        }

        // ---- softmax: P = 2^s (fp16x2 MUFU) ----
        uint32_t ph[2][4][2];
#pragma unroll
        for (int mi = 0; mi < 2; mi++)
#pragma unroll
            for (int jn = 0; jn < 4; jn++) {
                ph[mi][jn][0] = exp2_ph(s[mi][jn][0], s[mi][jn][1]);
                ph[mi][jn][1] = exp2_ph(s[mi][jn][2], s[mi][jn][3]);
            }

        // ---- l += P @ ones ----
#pragma unroll
        for (int mi = 0; mi < 2; mi++)
#pragma unroll
            for (int jk = 0; jk < 2; jk++)
                mma_f16(acc_l[mi],
                        ph[mi][2 * jk][0], ph[mi][2 * jk][1],
                        ph[mi][2 * jk + 1][0], ph[mi][2 * jk + 1][1],
                        ONES, ONES);

        // ---- O += P @ V (ldmatrix.x4: per jnd, 1 load covers both jk) ----
#pragma unroll
        for (int jnd = 0; jnd < 8; jnd++) {
            uint32_t vv[4];
            ldsm_x4(vv, vBase + (vs_off + (uint32_t)(jnd * 8 * 36)) * 4u);
#pragma unroll
            for (int jk = 0; jk < 2; jk++)
#pragma unroll
                for (int mi = 0; mi < 2; mi++)
                    mma_f16(acc_o[mi][jnd],
                            ph[mi][2 * jk][0], ph[mi][2 * jk][1],
                            ph[mi][2 * jk + 1][0], ph[mi][2 * jk + 1][1],
                            vv[jk * 2], vv[jk * 2 + 1]);
        }

        if (blk + 2 < nblk) ISSUE_BLK(blk + 2);
        asm volatile("cp.async.commit_group;" ::: "memory");
    }

    float l_loc[4];
#pragma unroll
    for (int mi = 0; mi < 2; mi++) {
        l_loc[2 * mi]     = acc_l[mi][0];
        l_loc[2 * mi + 1] = acc_l[mi][2];
    }

    // ---- cross-warp merge ----
    __syncthreads();
    float* OmS = (float*)smw;
    float* lS  = (float*)(smw + LS_W);
    const size_t head_off = (size_t)b * SEQ * DIM + (size_t)h * HDIM;
    if (wn == 1) {
#pragma unroll
        for (int mi = 0; mi < 2; mi++)
#pragma unroll
            for (int jnd = 0; jnd < 8; jnd++) {
                int r = 32 * wm + 16 * mi + g;
                int c = 8 * jnd + 2 * t;
                *(float2*)(&OmS[r * 68 + c]) =
                    make_float2(acc_o[mi][jnd][0], acc_o[mi][jnd][1]);
                *(float2*)(&OmS[(r + 8) * 68 + c]) =
                    make_float2(acc_o[mi][jnd][2], acc_o[mi][jnd][3]);
            }
        if (t == 0) {
            lS[32 * wm + g]      = l_loc[0];
            lS[32 * wm + 8 + g]  = l_loc[1];
            lS[32 * wm + 16 + g] = l_loc[2];
            lS[32 * wm + 24 + g] = l_loc[3];
        }
    }
    __syncthreads();
    if (wn == 0) {
        float* Obase = Op + head_off + (size_t)q0 * DIM;
#pragma unroll
        for (int mi = 0; mi < 2; mi++)
#pragma unroll
            for (int jnd = 0; jnd < 8; jnd++) {
                int r = 32 * wm + 16 * mi + g;
                int c = 8 * jnd + 2 * t;
                float2 p0 = *(const float2*)(&OmS[r * 68 + c]);
                float2 p1 = *(const float2*)(&OmS[(r + 8) * 68 + c]);
                *(float2*)(Obase + (size_t)r * DIM + c) =
                    make_float2(acc_o[mi][jnd][0] + p0.x, acc_o[mi][jnd][1] + p0.y);
                *(float2*)(Obase + (size_t)(r + 8) * DIM + c) =
                    make_float2(acc_o[mi][jnd][2] + p1.x, acc_o[mi][jnd][3] + p1.y);
            }
        if (t == 0) {
            int rows[4] = {32 * wm + g, 32 * wm + 8 + g, 32 * wm + 16 + g, 32 * wm + 24 + g};
#pragma unroll
            for (int sl = 0; sl < 4; sl++) {
                float ltot = l_loc[sl] + lS[rows[sl]];
                int grow = b * SEQ + q0 + rows[sl];
                Lg[(size_t)part * MTOT * NHEADS + (size_t)grow * NHEADS + h] = ltot;
            }
        }
    }
#undef ISSUE_BLK
#undef CP16
}

// ===========================================================================
// Merge + normalize the 3 kv-partitions
// ===========================================================================
__global__ __launch_bounds__(256) void merge_norm3(
    const float* __restrict__ O1, const float* __restrict__ O2,
    const float* __restrict__ O3, const float* __restrict__ Lg,
    float* __restrict__ Om)
{
    int f = blockIdx.x * 256 + threadIdx.x;
    int row = f / (DIM / 4);
    int c4  = (f % (DIM / 4)) * 4;
    int h   = c4 >> 6;
    size_t li = (size_t)row * NHEADS + h;
    float l = Lg[li] + Lg[(size_t)MTOT * NHEADS + li] + Lg[2ull * MTOT * NHEADS + li];
    float inv = 1.0f / l;
    float4 a = *(const float4*)(O1 + (size_t)f * 4);
    float4 bq = *(const float4*)(O2 + (size_t)f * 4);
    float4 c = *(const float4*)(O3 + (size_t)f * 4);
    float4 o;
    o.x = (a.x + bq.x + c.x) * inv;
    o.y = (a.y + bq.y + c.y) * inv;
    o.z = (a.z + bq.z + c.z) * inv;
    o.w = (a.w + bq.w + c.w) * inv;
    *(float4*)(Om + (size_t)f * 4) = o;
}

// ---------------------------------------------------------------------------
// Launch
// ---------------------------------------------------------------------------
extern "C" void kernel_launch(void* const* d_in, const int* in_sizes, int n_in,
                              void* d_out, int out_size)
{
    const float* xq = (const float*)d_in[0];
    const float* xk = (const float*)d_in[1];
    const float* xv = (const float*)d_in[2];
    const float* Wq = (const float*)d_in[3];
    const float* Wk = (const float*)d_in[4];
    const float* Wv = (const float*)d_in[5];
    const float* Wp = (const float*)d_in[6];
    const float* bp = (const float*)d_in[7];
    float* out = (float*)d_out;

    float *vb, *o1, *o2, *o3, *om, *lg;
    uint32_t *qhp, *khp, *vhp, *whp;
    cudaGetSymbolAddress((void**)&vb, g_V);
    cudaGetSymbolAddress((void**)&o1, g_O1);
    cudaGetSymbolAddress((void**)&o2, g_O2);
    cudaGetSymbolAddress((void**)&o3, g_O3);
    cudaGetSymbolAddress((void**)&om, g_OM);
    cudaGetSymbolAddress((void**)&lg, g_L);
    cudaGetSymbolAddress((void**)&qhp, g_QH);
    cudaGetSymbolAddress((void**)&khp, g_KH);
    cudaGetSymbolAddress((void**)&vhp, g_VtH);
    cudaGetSymbolAddress((void**)&whp, g_WH);

    const size_t WSTR = (size_t)DIM * (DIM / 2);

    w_split<<<dim3(DIM * DIM / 4 / 256, 4), 256>>>(Wq, Wk, Wv, Wp, whp);

    gemm3_v4<<<dim3(6, 64, 3), 256>>>(
        xq, whp,            nullptr, qhp, nullptr,
        xk, whp + WSTR,     nullptr, khp, nullptr,
        xv, whp + 2 * WSTR, vb, nullptr, nullptr,
        nullptr, 0x021);

    v_split_t<<<dim3(SEQ / 64, B * NHEADS), 256>>>(vb, vhp);

    const int fsm_bytes = FSMW * 4;   // 74240
    cudaFuncSetAttribute(flash_mma10,
                         cudaFuncAttributeMaxDynamicSharedMemorySize, fsm_bytes);
    flash_mma10<<<dim3(SEQ / FQ, NHEADS, B * KVPARTS), 256, fsm_bytes>>>(
        qhp, khp, vhp, o1, o2, o3, lg);

    merge_norm3<<<(MTOT * DIM / 4) / 256, 256>>>(o1, o2, o3, lg, om);

    gemm3_v4<<<dim3(6, 64, 1), 256>>>(
        om, whp + 3 * WSTR, out, nullptr, nullptr,
        om, whp + 3 * WSTR, out, nullptr, nullptr,
        om, whp + 3 * WSTR, out, nullptr, nullptr,
        bp, 0x000);
}